// round 13
// baseline (speedup 1.0000x reference)
#include <cuda_runtime.h>
#include <cstdint>

// Cost-volume correlation, MAX_DISP=4 (81 disps), kernel_size=1.
// out[b, dy*9+dx, y, x] = (1/C) * sum_c in1[b,c,y,x] * in2[b,c,y+dy-4,x+dx-4]
//
// R13: diagonal dy-pairing. Outputs (y, dy+1) and (y+1, dy) read the SAME in2
// row (y+dy-3), so each thread computes both from one 12-float window:
// LDS wavefronts per FMA halved vs R11, and in2/in1 global re-reads drop 9x->5x.
// Block(32,8): warp ty owns smem row ty (per-warp cp.async pipeline, __syncwarp
// only). Grid: (5 dy-groups, 17 y-strips, B). Group g covers dy=2g (diag1, row
// y+1) and dy=2g+1 (diag0, row y); g=4 stores only diag1 (dy=8).

typedef unsigned long long u64;

__device__ __forceinline__ void fma2(u64 &d, u64 a, u64 b) {
    asm("fma.rn.f32x2 %0, %1, %2, %0;" : "+l"(d) : "l"(a), "l"(b));
}
__device__ __forceinline__ u64 pk(float lo, float hi) {
    u64 r; asm("mov.b64 %0, {%1,%2};" : "=l"(r) : "f"(lo), "f"(hi)); return r;
}
__device__ __forceinline__ void upk(u64 v, float &lo, float &hi) {
    asm("mov.b64 {%0,%1}, %2;" : "=f"(lo), "=f"(hi) : "l"(v));
}
__device__ __forceinline__ void cpasync16(uint32_t d, const float* s) {
    asm volatile("cp.async.cg.shared.global [%0], [%1], 16;" :: "r"(d), "l"(s));
}

#define CC 128
#define HH 128
#define WW 128
#define HW (HH * WW)
#define NDISP 81
#define TILE_C 136                   // 128 px + 8 halo (floats per row)
#define ROW_F TILE_C
#define ROW_B (TILE_C * 4)           // 544 B
#define STAGE_F (8 * TILE_C)
#define STAGE_B (STAGE_F * 4)        // 4352 B
#define STAGES 4

__global__ __launch_bounds__(256, 2)
void corr_kernel(const float* __restrict__ in1,
                 const float* __restrict__ in2,
                 float* __restrict__ out)
{
    __shared__ __align__(16) float sm[STAGES * STAGE_F];

    const int tx = threadIdx.x;              // 0..31 (lane; warp = row ty)
    const int ty = threadIdx.y;              // 0..7
    const int g  = blockIdx.x;               // dy group 0..4
    const int b  = blockIdx.z;

    const int yb = blockIdx.y * 8 - 1 + ty;  // base row: diag0 y=yb, diag1 y=yb+1
    const int x  = tx * 4;                   // pixels x..x+3

    // in1 rows (clamped addresses; OOB results discarded at store time)
    const int ya  = min(max(yb, 0), HH - 1);
    const int yb1 = min(max(yb + 1, 0), HH - 1);
    const float* i1a = in1 + ((b * CC) * HH + ya)  * WW + x;   // diag0 (dy=2g+1)
    const float* i1b = in1 + ((b * CC) * HH + yb1) * WW + x;   // diag1 (dy=2g)

    // ---- per-warp staging: warp ty owns smem row ty = in2 row gy ----
    const int gy = yb + 2 * g - 3;           // shared window row for both diags
    const bool rowok = (gy >= 0) && (gy < HH);

    const uint32_t rowsb = (uint32_t)__cvta_generic_to_shared(sm) + ty * ROW_B;
    const int q0 = 2 * tx;                   // lanes 0..16 carry quads 0..33
    const int q1 = 2 * tx + 1;
    const bool ldr = (tx < 17);
    const bool ok0 = ldr && rowok && (q0 >= 1);
    const bool ok1 = ldr && rowok && (q1 <= 32);
    const float* i2r = in2 + (b * CC) * HW + gy * WW;
    const float* s0 = i2r + (4 * q0 - 4);    // quad q covers gx = 4q-4..4q-1
    const float* s1 = i2r + (4 * q1 - 4);
    const uint32_t d0 = rowsb + q0 * 16;
    const uint32_t d1 = rowsb + q1 * 16;

    // zero never-written (OOB) slots once, all stages (own row only)
    if (ldr) {
        float4 z = make_float4(0.f, 0.f, 0.f, 0.f);
        float* rowg = sm + ty * ROW_F;
#pragma unroll
        for (int s = 0; s < STAGES; s++) {
            if (!ok0) *(float4*)(rowg + s * STAGE_F + q0 * 4) = z;
            if (!ok1) *(float4*)(rowg + s * STAGE_F + q1 * 4) = z;
        }
    }

    // Prologue: channels 0..2 into stages 0..2.
#pragma unroll
    for (int c = 0; c < 3; c++) {
        const uint32_t o = c * STAGE_B;
        if (ok0) cpasync16(d0 + o, s0 + c * HW);
        if (ok1) cpasync16(d1 + o, s1 + c * HW);
        asm volatile("cp.async.commit_group;");
    }
    float4 aqa0 = *(const float4*)i1a;
    float4 aqa1 = *(const float4*)(i1a + HW);
    float4 aqb0 = *(const float4*)i1b;
    float4 aqb1 = *(const float4*)(i1b + HW);

    const float* i1an = i1a + 2 * HW;        // in1 row a, channel c+2
    const float* i1bn = i1b + 2 * HW;
    const float* s0n = s0 + 3 * HW;          // in2 channel c+3
    const float* s1n = s1 + 3 * HW;
    const float* smrow = sm + ty * ROW_F + x;   // window col0 (gx=x-4), stage 0

    // diag0 (y=yb, dy=2g+1): accE[0..9], accO[0..15]
    // diag1 (y=yb+1, dy=2g): accE[10..19], accO[16..31]
    u64   accE[20];
    float accO[32];
#pragma unroll
    for (int i = 0; i < 20; i++) accE[i] = 0ull;
#pragma unroll
    for (int i = 0; i < 32; i++) accO[i] = 0.f;

    for (int c4 = 0; c4 < CC; c4 += 4) {
#pragma unroll
        for (int u = 0; u < 4; u++) {
            const int c = c4 + u;
            asm volatile("cp.async.wait_group 2;" ::: "memory");
            __syncwarp();

            float4 na = make_float4(0.f, 0.f, 0.f, 0.f), nb = na;
            if (c + 2 < CC) {
                na = *(const float4*)i1an;  i1an += HW;
                nb = *(const float4*)i1bn;  i1bn += HW;
            }
            if (c + 3 < CC) {
                const uint32_t o = ((u + 3) & 3) * STAGE_B;
                if (ok0) cpasync16(d0 + o, s0n);
                if (ok1) cpasync16(d1 + o, s1n);
                s0n += HW; s1n += HW;
            }
            asm volatile("cp.async.commit_group;");

            // window w[0..11] = gx x-4..x+7 ; P[i] = packed (w[2i], w[2i+1])
            const ulonglong2* W = (const ulonglong2*)(smrow + u * STAGE_F);
            ulonglong2 Q0 = W[0], Q1 = W[1], Q2 = W[2];
            const u64 P0 = Q0.x, P1 = Q0.y, P2 = Q1.x, P3 = Q1.y, P4 = Q2.x, P5 = Q2.y;

            const u64 A0 = pk(aqa0.x, aqa0.y), A1 = pk(aqa0.z, aqa0.w);
            const u64 B0 = pk(aqb0.x, aqb0.y), B1 = pk(aqb0.z, aqb0.w);

            // even dx = 2k: accE[k*2+j] += {A,B}_j * P[k+j]
            fma2(accE[ 0], A0, P0); fma2(accE[ 1], A1, P1);
            fma2(accE[ 2], A0, P1); fma2(accE[ 3], A1, P2);
            fma2(accE[ 4], A0, P2); fma2(accE[ 5], A1, P3);
            fma2(accE[ 6], A0, P3); fma2(accE[ 7], A1, P4);
            fma2(accE[ 8], A0, P4); fma2(accE[ 9], A1, P5);
            fma2(accE[10], B0, P0); fma2(accE[11], B1, P1);
            fma2(accE[12], B0, P1); fma2(accE[13], B1, P2);
            fma2(accE[14], B0, P2); fma2(accE[15], B1, P3);
            fma2(accE[16], B0, P3); fma2(accE[17], B1, P4);
            fma2(accE[18], B0, P4); fma2(accE[19], B1, P5);

            // odd dx = 2t+1: operand(px p) = w[p + 2t+1]
            float l0,h0,l1,h1,l2,h2,l3,h3,l4,h4,l5,h5;
            upk(P0,l0,h0); upk(P1,l1,h1); upk(P2,l2,h2);
            upk(P3,l3,h3); upk(P4,l4,h4); upk(P5,l5,h5);
            {
                const float a0 = aqa0.x, a1 = aqa0.y, a2 = aqa0.z, a3 = aqa0.w;
                accO[ 0] = fmaf(a0, h0, accO[ 0]);
                accO[ 1] = fmaf(a1, l1, accO[ 1]);
                accO[ 2] = fmaf(a2, h1, accO[ 2]);
                accO[ 3] = fmaf(a3, l2, accO[ 3]);
                accO[ 4] = fmaf(a0, h1, accO[ 4]);
                accO[ 5] = fmaf(a1, l2, accO[ 5]);
                accO[ 6] = fmaf(a2, h2, accO[ 6]);
                accO[ 7] = fmaf(a3, l3, accO[ 7]);
                accO[ 8] = fmaf(a0, h2, accO[ 8]);
                accO[ 9] = fmaf(a1, l3, accO[ 9]);
                accO[10] = fmaf(a2, h3, accO[10]);
                accO[11] = fmaf(a3, l4, accO[11]);
                accO[12] = fmaf(a0, h3, accO[12]);
                accO[13] = fmaf(a1, l4, accO[13]);
                accO[14] = fmaf(a2, h4, accO[14]);
                accO[15] = fmaf(a3, l5, accO[15]);
            }
            {
                const float b0 = aqb0.x, b1 = aqb0.y, b2 = aqb0.z, b3 = aqb0.w;
                accO[16] = fmaf(b0, h0, accO[16]);
                accO[17] = fmaf(b1, l1, accO[17]);
                accO[18] = fmaf(b2, h1, accO[18]);
                accO[19] = fmaf(b3, l2, accO[19]);
                accO[20] = fmaf(b0, h1, accO[20]);
                accO[21] = fmaf(b1, l2, accO[21]);
                accO[22] = fmaf(b2, h2, accO[22]);
                accO[23] = fmaf(b3, l3, accO[23]);
                accO[24] = fmaf(b0, h2, accO[24]);
                accO[25] = fmaf(b1, l3, accO[25]);
                accO[26] = fmaf(b2, h3, accO[26]);
                accO[27] = fmaf(b3, l4, accO[27]);
                accO[28] = fmaf(b0, h3, accO[28]);
                accO[29] = fmaf(b1, l4, accO[29]);
                accO[30] = fmaf(b2, h4, accO[30]);
                accO[31] = fmaf(b3, l5, accO[31]);
            }

            aqa0 = aqa1; aqa1 = na;
            aqb0 = aqb1; aqb1 = nb;
        }
    }

    // ---- epilogue: mean over C, float4 stores ----
    const float s = 1.0f / (float)CC;

    // diag0: y=yb, dy=2g+1 (store only if g<4 and yb in range)
    if (g < 4 && yb >= 0 && yb < HH) {
        float* ob = out + ((b * NDISP + (2 * g + 1) * 9) * HH + yb) * WW + x;
#pragma unroll
        for (int k = 0; k < 5; k++) {
            float e0, e1, e2, e3;
            upk(accE[k * 2 + 0], e0, e1);
            upk(accE[k * 2 + 1], e2, e3);
            *(float4*)(ob + 2 * k * HW) = make_float4(e0*s, e1*s, e2*s, e3*s);
        }
#pragma unroll
        for (int t = 0; t < 4; t++) {
            *(float4*)(ob + (2 * t + 1) * HW) =
                make_float4(accO[t*4+0]*s, accO[t*4+1]*s,
                            accO[t*4+2]*s, accO[t*4+3]*s);
        }
    }
    // diag1: y=yb+1, dy=2g (store if yb+1 in range)
    if (yb + 1 >= 0 && yb + 1 < HH) {
        float* ob = out + ((b * NDISP + (2 * g) * 9) * HH + (yb + 1)) * WW + x;
#pragma unroll
        for (int k = 0; k < 5; k++) {
            float e0, e1, e2, e3;
            upk(accE[10 + k * 2 + 0], e0, e1);
            upk(accE[10 + k * 2 + 1], e2, e3);
            *(float4*)(ob + 2 * k * HW) = make_float4(e0*s, e1*s, e2*s, e3*s);
        }
#pragma unroll
        for (int t = 0; t < 4; t++) {
            *(float4*)(ob + (2 * t + 1) * HW) =
                make_float4(accO[16 + t*4+0]*s, accO[16 + t*4+1]*s,
                            accO[16 + t*4+2]*s, accO[16 + t*4+3]*s);
        }
    }
}

extern "C" void kernel_launch(void* const* d_in, const int* in_sizes, int n_in,
                              void* d_out, int out_size)
{
    const float* in1 = (const float*)d_in[0];
    const float* in2 = (const float*)d_in[1];
    float* out = (float*)d_out;

    const int B = in_sizes[0] / (CC * HH * WW);   // 8

    dim3 block(32, 8);
    dim3 grid(5, 17, B);     // dy-groups, y-strips (yb = 8*by-1+ty in -1..134), batch
    corr_kernel<<<grid, block>>>(in1, in2, out);
}

// round 14
// speedup vs baseline: 1.3531x; 1.3531x over previous
#include <cuda_runtime.h>
#include <cstdint>

// Cost-volume correlation, MAX_DISP=4 (81 disps), kernel_size=1.
// out[b, dy*9+dx, y, x] = (1/C) * sum_c in1[b,c,y,x] * in2[b,c,y+dy-4,x+dx-4]
//
// R14 = R11 structure (warp owns its row, per-warp cp.async pipeline,
// __syncwarp only, 4px/thread, f32x2 even-dx + scalar odd-dx) with the latency
// fixes: 8-stage ring (wait_group 6, prefetch distance 7), in1 queue depth 3,
// channel loop unrolled x8 (constant ring offsets), merged s1/d1 pointers.

typedef unsigned long long u64;

__device__ __forceinline__ void fma2(u64 &d, u64 a, u64 b) {
    asm("fma.rn.f32x2 %0, %1, %2, %0;" : "+l"(d) : "l"(a), "l"(b));
}
__device__ __forceinline__ u64 pk(float lo, float hi) {
    u64 r; asm("mov.b64 %0, {%1,%2};" : "=l"(r) : "f"(lo), "f"(hi)); return r;
}
__device__ __forceinline__ void upk(u64 v, float &lo, float &hi) {
    asm("mov.b64 {%0,%1}, %2;" : "=f"(lo), "=f"(hi) : "l"(v));
}
__device__ __forceinline__ void cpasync16(uint32_t d, const float* s) {
    asm volatile("cp.async.cg.shared.global [%0], [%1], 16;" :: "r"(d), "l"(s));
}

#define CC 128
#define HH 128
#define WW 128
#define HW (HH * WW)
#define NDISP 81
#define TILE_C 136                   // 128 px + 8 halo (floats per row)
#define ROW_F TILE_C
#define ROW_B (TILE_C * 4)           // 544 B
#define STAGE_F (8 * TILE_C)         // 8 warp-rows per stage
#define STAGE_B (STAGE_F * 4)        // 4352 B
#define STAGES 8                     // ring depth (34816 B total)

__global__ __launch_bounds__(256, 3)
void corr_kernel(const float* __restrict__ in1,
                 const float* __restrict__ in2,
                 float* __restrict__ out)
{
    __shared__ __align__(16) float sm[STAGES * STAGE_F];

    const int tx = threadIdx.x;              // 0..31
    const int ty = threadIdx.y;              // 0..7 (= warp id = y row = smem row)
    const int dy = blockIdx.x;               // 0..8
    const int y0 = blockIdx.y * 8;
    const int b  = blockIdx.z;

    const int y = y0 + ty;
    const int x = tx * 4;                    // pixels x..x+3

    const float* i1 = in1 + ((b * CC) * HH + y) * WW + x;

    // ---- per-warp staging: warp ty loads row gy = y0+ty+dy-4 (34 quads) ----
    const int gy = y0 + ty + dy - 4;
    const bool rowok = (gy >= 0) && (gy < HH);

    const uint32_t rowsb = (uint32_t)__cvta_generic_to_shared(sm) + ty * ROW_B;
    const int q0 = 2 * tx;                   // lanes 0..16 carry quads 0..33
    const bool ldr = (tx < 17);
    const bool ok0 = ldr && rowok && (q0 >= 1);        // q0 <= 32 automatic
    const bool ok1 = ldr && rowok && (q0 + 1 <= 32);   // q1 >= 1 automatic
    const float* i2r = in2 + (b * CC) * HW + gy * WW;
    const float* s0 = i2r + (4 * q0 - 4);    // quad q covers gx = 4q-4 .. 4q-1
    const uint32_t d0 = rowsb + q0 * 16;     // s1 = s0 + 4 floats, d1 = d0 + 16

    // zero never-written (OOB) slots once, all stages (own row only)
    if (ldr) {
        float4 z = make_float4(0.f, 0.f, 0.f, 0.f);
        float* rowg = sm + ty * ROW_F;
#pragma unroll
        for (int s = 0; s < STAGES; s++) {
            if (!ok0) *(float4*)(rowg + s * STAGE_F + q0 * 4) = z;
            if (!ok1) *(float4*)(rowg + s * STAGE_F + q0 * 4 + 4) = z;
        }
    }

    // Prologue: channels 0..6 into stages 0..6 (one commit group each).
#pragma unroll
    for (int c = 0; c < 7; c++) {
        const uint32_t o = c * STAGE_B;
        if (ok0) cpasync16(d0 + o,      s0 + c * HW);
        if (ok1) cpasync16(d0 + o + 16, s0 + c * HW + 4);
        asm volatile("cp.async.commit_group;");
    }
    float4 aq0 = *(const float4*)i1;
    float4 aq1 = *(const float4*)(i1 + HW);
    float4 aq2 = *(const float4*)(i1 + 2 * HW);

    const float* i1n = i1 + 3 * HW;          // in1 channel c+3
    const float* s0n = s0 + 7 * HW;          // in2 channel c+7
    const float* smrow = sm + ty * ROW_F + x;   // window col0 (gx=x-4), stage 0

    u64   accE[10];                          // even dx: [k]=(x,x+1), [5+k]=(x+2,x+3)
    float accO[16];                          // odd dx 2t+1: [t*4+p] = pixel x+p
#pragma unroll
    for (int i = 0; i < 10; i++) accE[i] = 0ull;
#pragma unroll
    for (int i = 0; i < 16; i++) accO[i] = 0.f;

    for (int c8 = 0; c8 < CC; c8 += 8) {
#pragma unroll
        for (int u = 0; u < 8; u++) {
            const int c = c8 + u;
            asm volatile("cp.async.wait_group 6;" ::: "memory");
            __syncwarp();   // all lanes' stage-c loads visible; stage (c+7)&7 free

            float4 an = make_float4(0.f, 0.f, 0.f, 0.f);
            if (c + 3 < CC) { an = *(const float4*)i1n; i1n += HW; }
            if (c + 7 < CC) {
                const uint32_t o = ((u + 7) & 7) * STAGE_B;   // immediate per u
                if (ok0) cpasync16(d0 + o,      s0n);
                if (ok1) cpasync16(d0 + o + 16, s0n + 4);
                s0n += HW;
            }
            asm volatile("cp.async.commit_group;");

            const u64 A01 = pk(aq0.x, aq0.y);
            const u64 A23 = pk(aq0.z, aq0.w);

            // window w[0..11] = gx x-4..x+7 ; P[i] = packed (w[2i], w[2i+1])
            const ulonglong2* W = (const ulonglong2*)(smrow + u * STAGE_F);
            ulonglong2 Q0 = W[0], Q1 = W[1], Q2 = W[2];
            const u64 P0 = Q0.x, P1 = Q0.y, P2 = Q1.x, P3 = Q1.y, P4 = Q2.x, P5 = Q2.y;

            // even dx = 2k
            fma2(accE[0], A01, P0);  fma2(accE[5], A23, P1);
            fma2(accE[1], A01, P1);  fma2(accE[6], A23, P2);
            fma2(accE[2], A01, P2);  fma2(accE[7], A23, P3);
            fma2(accE[3], A01, P3);  fma2(accE[8], A23, P4);
            fma2(accE[4], A01, P4);  fma2(accE[9], A23, P5);

            // odd dx = 2t+1 via register halves
            float l0,h0,l1,h1,l2,h2,l3,h3,l4,h4,l5,h5;
            upk(P0,l0,h0); upk(P1,l1,h1); upk(P2,l2,h2);
            upk(P3,l3,h3); upk(P4,l4,h4); upk(P5,l5,h5);
            const float a0 = aq0.x, a1 = aq0.y, a2 = aq0.z, a3 = aq0.w;
            accO[ 0] = fmaf(a0, h0, accO[ 0]);
            accO[ 1] = fmaf(a1, l1, accO[ 1]);
            accO[ 2] = fmaf(a2, h1, accO[ 2]);
            accO[ 3] = fmaf(a3, l2, accO[ 3]);
            accO[ 4] = fmaf(a0, h1, accO[ 4]);
            accO[ 5] = fmaf(a1, l2, accO[ 5]);
            accO[ 6] = fmaf(a2, h2, accO[ 6]);
            accO[ 7] = fmaf(a3, l3, accO[ 7]);
            accO[ 8] = fmaf(a0, h2, accO[ 8]);
            accO[ 9] = fmaf(a1, l3, accO[ 9]);
            accO[10] = fmaf(a2, h3, accO[10]);
            accO[11] = fmaf(a3, l4, accO[11]);
            accO[12] = fmaf(a0, h3, accO[12]);
            accO[13] = fmaf(a1, l4, accO[13]);
            accO[14] = fmaf(a2, h4, accO[14]);
            accO[15] = fmaf(a3, l5, accO[15]);

            aq0 = aq1; aq1 = aq2; aq2 = an;
        }
    }

    // ---- epilogue: mean over C, float4 stores ----
    const float s = 1.0f / (float)CC;
    float* ob = out + ((b * NDISP + dy * 9) * HH + y) * WW + x;
#pragma unroll
    for (int k = 0; k < 5; k++) {            // even dx = 2k
        float e0, e1, e2, e3;
        upk(accE[k],     e0, e1);
        upk(accE[5 + k], e2, e3);
        *(float4*)(ob + (2 * k) * HW) =
            make_float4(e0 * s, e1 * s, e2 * s, e3 * s);
    }
#pragma unroll
    for (int t = 0; t < 4; t++) {            // odd dx = 2t+1
        *(float4*)(ob + (2 * t + 1) * HW) =
            make_float4(accO[t * 4 + 0] * s, accO[t * 4 + 1] * s,
                        accO[t * 4 + 2] * s, accO[t * 4 + 3] * s);
    }
}

extern "C" void kernel_launch(void* const* d_in, const int* in_sizes, int n_in,
                              void* d_out, int out_size)
{
    const float* in1 = (const float*)d_in[0];
    const float* in2 = (const float*)d_in[1];
    float* out = (float*)d_out;

    const int B = in_sizes[0] / (CC * HH * WW);   // 8

    dim3 block(32, 8);
    dim3 grid(9, HH / 8, B);
    corr_kernel<<<grid, block>>>(in1, in2, out);
}